// round 9
// baseline (speedup 1.0000x reference)
#include <cuda_runtime.h>
#include <cstdint>

#define D 128
#define NMAX 50000
#define EMAX 800000

// ---------------- scratch (static device globals; no allocation) ----------------
__device__ float g_H [(size_t)NMAX * D];   // GEMM output per layer
__device__ float g_A [(size_t)NMAX * D];   // layer activations (ping)
__device__ float g_B [(size_t)NMAX * D];   // layer activations (pong)
__device__ float g_dinv[NMAX];
__device__ int   g_cnt[NMAX];
__device__ int   g_rowstart[NMAX + 1];
__device__ int   g_cursor[NMAX];
__device__ int2  g_cw[EMAX];               // packed (src, weight-bits)
__device__ unsigned long long g_desc[64];  // lookback descriptors: flag<<32 | value

// ---------------- tf32 helpers ----------------
__device__ __forceinline__ void tf32_split(float x, float& h, float& l) {
    uint32_t hb; asm("cvt.rna.tf32.f32 %0, %1;" : "=r"(hb) : "f"(x));
    h = __uint_as_float(hb);
    float r = x - h;
    uint32_t lb; asm("cvt.rna.tf32.f32 %0, %1;" : "=r"(lb) : "f"(r));
    l = __uint_as_float(lb);
}

__device__ __forceinline__ void mma_tf32(float* c, const uint32_t* a,
                                         uint32_t b0, uint32_t b1) {
    asm volatile(
        "mma.sync.aligned.m16n8k8.row.col.f32.tf32.tf32.f32 "
        "{%0,%1,%2,%3}, {%4,%5,%6,%7}, {%8,%9}, {%0,%1,%2,%3};"
        : "+f"(c[0]), "+f"(c[1]), "+f"(c[2]), "+f"(c[3])
        : "r"(a[0]), "r"(a[1]), "r"(a[2]), "r"(a[3]), "r"(b0), "r"(b1));
}

// ---------------- CSR construction ----------------
__global__ void k_zero2(int n) {
    int i = blockIdx.x * blockDim.x + threadIdx.x;
    if (i < n) g_cnt[i] = 0;
    if (i < 64) g_desc[i] = 0ULL;
}

__global__ void k_count(const int* __restrict__ dst, int E) {
    int base = (blockIdx.x * blockDim.x + threadIdx.x) * 4;
    if (base >= E) return;
    if (base + 3 < E) {
        int4 d = *(const int4*)(dst + base);
        atomicAdd(&g_cnt[d.x], 1);
        atomicAdd(&g_cnt[d.y], 1);
        atomicAdd(&g_cnt[d.z], 1);
        atomicAdd(&g_cnt[d.w], 1);
    } else {
        for (int j = base; j < E; j++) atomicAdd(&g_cnt[dst[j]], 1);
    }
}

// single-pass exclusive scan via decoupled lookback; writes rowstart/cursor/dinv.
// 49 blocks (<=148 SMs) are co-resident; each block only waits on lower ids.
__global__ void k_scan_lb(int n) {
    __shared__ int wsum[32];
    __shared__ int s_prefix;
    int tid = threadIdx.x, lane = tid & 31, wid = tid >> 5;
    int b = blockIdx.x;
    int i = b * 1024 + tid;
    int v = (i < n) ? g_cnt[i] : 0;
    int x = v;
    #pragma unroll
    for (int o = 1; o < 32; o <<= 1) {
        int t = __shfl_up_sync(0xffffffffu, x, o);
        if (lane >= o) x += t;
    }
    if (lane == 31) wsum[wid] = x;
    __syncthreads();
    if (wid == 0) {
        int w = wsum[lane];
        #pragma unroll
        for (int o = 1; o < 32; o <<= 1) {
            int t = __shfl_up_sync(0xffffffffu, w, o);
            if (lane >= o) w += t;
        }
        wsum[lane] = w;
    }
    __syncthreads();
    int blockAgg = wsum[31];

    if (tid == 0) {
        if (b == 0) {
            s_prefix = 0;
            atomicExch(&g_desc[0], (2ULL << 32) | (unsigned)blockAgg);
        } else {
            atomicExch(&g_desc[b], (1ULL << 32) | (unsigned)blockAgg);
        }
    }
    if (b > 0 && wid == 0) {
        int prefix = 0;
        int look = b - 1;
        while (true) {
            int idx = look - lane;
            unsigned f; int val;
            if (idx >= 0) {
                unsigned long long d = atomicAdd(&g_desc[idx], 0ULL);
                f = (unsigned)(d >> 32);
                val = (int)(unsigned)d;
            } else { f = 1u; val = 0; }
            if (__ballot_sync(0xffffffffu, f == 0u)) continue;   // retry window
            unsigned bp = __ballot_sync(0xffffffffu, idx >= 0 && f == 2u);
            int stop = bp ? (__ffs(bp) - 1) : 32;
            int xs = (lane <= stop) ? val : 0;
            #pragma unroll
            for (int o = 16; o > 0; o >>= 1)
                xs += __shfl_xor_sync(0xffffffffu, xs, o);
            prefix += xs;
            if (stop < 32) break;
            look -= 32;
        }
        if (lane == 0) {
            s_prefix = prefix;
            atomicExch(&g_desc[b], (2ULL << 32) | (unsigned)(prefix + blockAgg));
        }
    }
    __syncthreads();

    int excl = s_prefix + (wid ? wsum[wid - 1] : 0) + x - v;
    if (i < n) {
        g_rowstart[i] = excl;
        g_cursor[i]   = excl;
        g_dinv[i]     = rsqrtf((float)(v + 1));   // deg incl. self-loop
        if (i == n - 1) g_rowstart[n] = excl + v;
    }
}

__global__ void k_fill(const int* __restrict__ ei, int E) {
    int base = (blockIdx.x * blockDim.x + threadIdx.x) * 4;
    if (base >= E) return;
    if (base + 3 < E) {
        int4 s = *(const int4*)(ei + base);
        int4 d = *(const int4*)(ei + E + base);
        int ss[4] = {s.x, s.y, s.z, s.w};
        int ds[4] = {d.x, d.y, d.z, d.w};
        float ws[4];
        #pragma unroll
        for (int j = 0; j < 4; j++) ws[j] = g_dinv[ss[j]] * g_dinv[ds[j]];
        #pragma unroll
        for (int j = 0; j < 4; j++) {
            int p = atomicAdd(&g_cursor[ds[j]], 1);
            g_cw[p] = make_int2(ss[j], __float_as_int(ws[j]));
        }
    } else {
        for (int j = base; j < E; j++) {
            int sj = ei[j], dj = ei[E + j];
            float w = g_dinv[sj] * g_dinv[dj];
            int p = atomicAdd(&g_cursor[dj], 1);
            g_cw[p] = make_int2(sj, __float_as_int(w));
        }
    }
}

// ---------------- GEMM: H[M x 128] = X @ W via 3xTF32 mma.m16n8k8 ----------------
// Block tile M=128, N=128, K chunked at 32 (smem ~70KB -> 2 CTAs/SM).
// 8 warps: 4(M) x 2(N); warp tile 32x64.
#define SXS2 36    // X smem row stride: A-frag bank = (4g+t)%32, bijective
#define SWS2 136   // W smem row stride: B-frag bank = (8t+g)%32, bijective
#define GEMM_SMEM ((2 * 128 * SXS2 + 2 * 32 * SWS2) * (int)sizeof(float))

__global__ __launch_bounds__(256, 2)
void k_gemm_mma(const float* __restrict__ X, const float* __restrict__ W,
                float* __restrict__ H, int M) {
    extern __shared__ float sm[];
    float* sXh = sm;
    float* sXl = sXh + 128 * SXS2;
    float* sWh = sXl + 128 * SXS2;
    float* sWl = sWh + 32 * SWS2;

    const int tid  = threadIdx.x;
    const int lane = tid & 31;
    const int g    = lane >> 2;
    const int t    = lane & 3;
    const int warp = tid >> 5;
    const int wm   = (warp >> 1) * 32;   // warp M offset
    const int wn   = (warp & 1) * 64;    // warp N offset
    const int row0 = blockIdx.x * 128;

    float acc[2][8][4];
    #pragma unroll
    for (int a = 0; a < 2; a++)
        #pragma unroll
        for (int b = 0; b < 8; b++)
            #pragma unroll
            for (int c = 0; c < 4; c++) acc[a][b][c] = 0.f;

    #pragma unroll
    for (int kc = 0; kc < 4; kc++) {
        // X chunk [128 rows][32 k]: 1024 float4 in 4 iters
        #pragma unroll
        for (int it = 0; it < 4; it++) {
            int e4 = tid + it * 256;
            int r  = e4 >> 3;
            int c4 = (e4 & 7) * 4;
            float4 v = make_float4(0.f, 0.f, 0.f, 0.f);
            if (row0 + r < M)
                v = *(const float4*)&X[(size_t)(row0 + r) * D + kc * 32 + c4];
            float4 h, l;
            tf32_split(v.x, h.x, l.x);
            tf32_split(v.y, h.y, l.y);
            tf32_split(v.z, h.z, l.z);
            tf32_split(v.w, h.w, l.w);
            *(float4*)&sXh[r * SXS2 + c4] = h;
            *(float4*)&sXl[r * SXS2 + c4] = l;
        }
        // W chunk [32 k][128 n]: 1024 float4 in 4 iters
        #pragma unroll
        for (int it = 0; it < 4; it++) {
            int e4 = tid + it * 256;
            int r  = e4 >> 5;
            int c4 = (e4 & 31) * 4;
            float4 v = *(const float4*)&W[(size_t)(kc * 32 + r) * D + c4];
            float4 h, l;
            tf32_split(v.x, h.x, l.x);
            tf32_split(v.y, h.y, l.y);
            tf32_split(v.z, h.z, l.z);
            tf32_split(v.w, h.w, l.w);
            *(float4*)&sWh[r * SWS2 + c4] = h;
            *(float4*)&sWl[r * SWS2 + c4] = l;
        }
        __syncthreads();

        #pragma unroll
        for (int ks = 0; ks < 4; ks++) {
            int k0 = ks * 8;
            uint32_t ah[2][4], al[2][4];
            #pragma unroll
            for (int mi = 0; mi < 2; mi++) {
                int mb = wm + mi * 16;
                ah[mi][0] = __float_as_uint(sXh[(mb + g)     * SXS2 + k0 + t]);
                ah[mi][1] = __float_as_uint(sXh[(mb + g + 8) * SXS2 + k0 + t]);
                ah[mi][2] = __float_as_uint(sXh[(mb + g)     * SXS2 + k0 + t + 4]);
                ah[mi][3] = __float_as_uint(sXh[(mb + g + 8) * SXS2 + k0 + t + 4]);
                al[mi][0] = __float_as_uint(sXl[(mb + g)     * SXS2 + k0 + t]);
                al[mi][1] = __float_as_uint(sXl[(mb + g + 8) * SXS2 + k0 + t]);
                al[mi][2] = __float_as_uint(sXl[(mb + g)     * SXS2 + k0 + t + 4]);
                al[mi][3] = __float_as_uint(sXl[(mb + g + 8) * SXS2 + k0 + t + 4]);
            }
            #pragma unroll
            for (int j = 0; j < 8; j++) {
                int nb = wn + j * 8;
                uint32_t bh0 = __float_as_uint(sWh[(k0 + t)     * SWS2 + nb + g]);
                uint32_t bh1 = __float_as_uint(sWh[(k0 + t + 4) * SWS2 + nb + g]);
                uint32_t bl0 = __float_as_uint(sWl[(k0 + t)     * SWS2 + nb + g]);
                uint32_t bl1 = __float_as_uint(sWl[(k0 + t + 4) * SWS2 + nb + g]);
                #pragma unroll
                for (int mi = 0; mi < 2; mi++) {
                    mma_tf32(acc[mi][j], ah[mi], bh0, bh1);
                    mma_tf32(acc[mi][j], ah[mi], bl0, bl1);
                    mma_tf32(acc[mi][j], al[mi], bh0, bh1);
                }
            }
        }
        __syncthreads();
    }

    #pragma unroll
    for (int mi = 0; mi < 2; mi++) {
        int r0 = row0 + wm + mi * 16 + g;
        #pragma unroll
        for (int j = 0; j < 8; j++) {
            int col = wn + j * 8 + 2 * t;
            if (r0 < M)
                *(float2*)&H[(size_t)r0 * D + col] =
                    make_float2(acc[mi][j][0], acc[mi][j][1]);
            if (r0 + 8 < M)
                *(float2*)&H[(size_t)(r0 + 8) * D + col] =
                    make_float2(acc[mi][j][2], acc[mi][j][3]);
        }
    }
}

// ---------------- aggregation: Y[n] = relu?( dinv^2*H[n] + sum w_i*H[col_i] + b )
__global__ void k_agg(const float* __restrict__ bias, float* __restrict__ Y,
                      int n, int do_relu) {
    int gt   = blockIdx.x * blockDim.x + threadIdx.x;
    int node = gt >> 5;
    int lane = gt & 31;
    if (node >= n) return;

    const float4* H4 = (const float4*)g_H;
    float di = g_dinv[node];
    float4 acc = H4[(size_t)node * 32 + lane];
    float sw = di * di;
    acc.x *= sw; acc.y *= sw; acc.z *= sw; acc.w *= sw;

    int i   = g_rowstart[node];
    int end = g_rowstart[node + 1];
    for (; i + 1 < end; i += 2) {
        int2  e0 = g_cw[i];
        int2  e1 = g_cw[i + 1];
        float w0 = __int_as_float(e0.y);
        float w1 = __int_as_float(e1.y);
        float4 h0 = H4[(size_t)e0.x * 32 + lane];
        float4 h1 = H4[(size_t)e1.x * 32 + lane];
        acc.x += w0 * h0.x + w1 * h1.x;
        acc.y += w0 * h0.y + w1 * h1.y;
        acc.z += w0 * h0.z + w1 * h1.z;
        acc.w += w0 * h0.w + w1 * h1.w;
    }
    if (i < end) {
        int2  e = g_cw[i];
        float w = __int_as_float(e.y);
        float4 h = H4[(size_t)e.x * 32 + lane];
        acc.x += w * h.x; acc.y += w * h.y; acc.z += w * h.z; acc.w += w * h.w;
    }

    float4 b4 = ((const float4*)bias)[lane];
    acc.x += b4.x; acc.y += b4.y; acc.z += b4.z; acc.w += b4.w;
    if (do_relu) {
        acc.x = fmaxf(acc.x, 0.f); acc.y = fmaxf(acc.y, 0.f);
        acc.z = fmaxf(acc.z, 0.f); acc.w = fmaxf(acc.w, 0.f);
    }
    ((float4*)Y)[(size_t)node * 32 + lane] = acc;
}

// ---------------- decoder: out[e] = dot(X[u], X[v]) ----------------
__global__ void k_decode(const float* __restrict__ X, const int* __restrict__ eli,
                         float* __restrict__ out, int EL) {
    int gt   = blockIdx.x * blockDim.x + threadIdx.x;
    int e    = gt >> 5;
    int lane = gt & 31;
    if (e >= EL) return;
    int u = eli[e];
    int v = eli[EL + e];
    const float4* X4 = (const float4*)X;
    float4 a = X4[(size_t)u * 32 + lane];
    float4 b = X4[(size_t)v * 32 + lane];
    float s = a.x * b.x + a.y * b.y + a.z * b.z + a.w * b.w;
    #pragma unroll
    for (int o = 16; o > 0; o >>= 1) s += __shfl_xor_sync(0xffffffffu, s, o);
    if (lane == 0) out[e] = s;
}

// ---------------- launch ----------------
extern "C" void kernel_launch(void* const* d_in, const int* in_sizes, int n_in,
                              void* d_out, int out_size) {
    const float* x   = (const float*)d_in[0];
    const float* W1  = (const float*)d_in[1];
    const float* b1  = (const float*)d_in[2];
    const float* W2  = (const float*)d_in[3];
    const float* b2  = (const float*)d_in[4];
    const float* W3  = (const float*)d_in[5];
    const float* b3  = (const float*)d_in[6];
    const int*   ei  = (const int*)d_in[7];
    const int*   eli = (const int*)d_in[8];
    float*       out = (float*)d_out;

    int N  = in_sizes[0] / D;
    int E  = in_sizes[7] / 2;
    int EL = in_sizes[8] / 2;

    float *pH, *pA, *pB;
    cudaGetSymbolAddress((void**)&pH, g_H);
    cudaGetSymbolAddress((void**)&pA, g_A);
    cudaGetSymbolAddress((void**)&pB, g_B);

    cudaFuncSetAttribute(k_gemm_mma, cudaFuncAttributeMaxDynamicSharedMemorySize,
                         GEMM_SMEM);

    // ---- CSR build (once; shared by all 3 layers) ----
    int nb = (N + 1023) / 1024;
    k_zero2<<<(N + 255) / 256, 256>>>(N);
    k_count<<<(E / 4 + 255) / 256, 256>>>(ei + E, E);
    k_scan_lb<<<nb, 1024>>>(N);
    k_fill<<<(E / 4 + 255) / 256, 256>>>(ei, E);

    int gemm_blocks = (N + 127) / 128;
    int agg_blocks  = (int)(((size_t)N * 32 + 255) / 256);

    // ---- layer 1 ----
    k_gemm_mma<<<gemm_blocks, 256, GEMM_SMEM>>>(x, W1, pH, N);
    k_agg<<<agg_blocks, 256>>>(b1, pA, N, 1);

    // ---- layer 2 ----
    k_gemm_mma<<<gemm_blocks, 256, GEMM_SMEM>>>(pA, W2, pH, N);
    k_agg<<<agg_blocks, 256>>>(b2, pB, N, 1);

    // ---- layer 3 (no relu) ----
    k_gemm_mma<<<gemm_blocks, 256, GEMM_SMEM>>>(pB, W3, pH, N);
    k_agg<<<agg_blocks, 256>>>(b3, pA, N, 0);

    // ---- decoder ----
    k_decode<<<(int)(((size_t)EL * 32 + 255) / 256), 256>>>(pA, eli, out, EL);
}

// round 10
// speedup vs baseline: 1.3722x; 1.3722x over previous
#include <cuda_runtime.h>
#include <cstdint>

#define D 128
#define NMAX 50000
#define EMAX 800000

// ---------------- scratch (static device globals; no allocation) ----------------
__device__ float g_H [(size_t)NMAX * D];   // GEMM output per layer
__device__ float g_A [(size_t)NMAX * D];   // layer activations (ping)
__device__ float g_B [(size_t)NMAX * D];   // layer activations (pong)
__device__ float g_dinv[NMAX];
__device__ int   g_cnt[NMAX];
__device__ int   g_rowstart[NMAX + 1];
__device__ int   g_cursor[NMAX];
__device__ int2  g_cw[EMAX];               // packed (src, weight-bits)
__device__ int   g_bsum[64];               // block sums for scan

// ---------------- tf32 helpers ----------------
__device__ __forceinline__ void tf32_split(float x, float& h, float& l) {
    uint32_t hb; asm("cvt.rna.tf32.f32 %0, %1;" : "=r"(hb) : "f"(x));
    h = __uint_as_float(hb);
    float r = x - h;
    uint32_t lb; asm("cvt.rna.tf32.f32 %0, %1;" : "=r"(lb) : "f"(r));
    l = __uint_as_float(lb);
}

__device__ __forceinline__ void mma_tf32(float* c, const uint32_t* a,
                                         uint32_t b0, uint32_t b1) {
    asm volatile(
        "mma.sync.aligned.m16n8k8.row.col.f32.tf32.tf32.f32 "
        "{%0,%1,%2,%3}, {%4,%5,%6,%7}, {%8,%9}, {%0,%1,%2,%3};"
        : "+f"(c[0]), "+f"(c[1]), "+f"(c[2]), "+f"(c[3])
        : "r"(a[0]), "r"(a[1]), "r"(a[2]), "r"(a[3]), "r"(b0), "r"(b1));
}

// ---------------- CSR construction ----------------
__global__ void k_zero_cnt(int n) {
    int i = blockIdx.x * blockDim.x + threadIdx.x;
    if (i < n) g_cnt[i] = 0;
}

__global__ void k_count(const int* __restrict__ dst, int E) {
    int base = (blockIdx.x * blockDim.x + threadIdx.x) * 8;
    if (base >= E) return;
    if (base + 7 < E) {
        int4 d0 = *(const int4*)(dst + base);
        int4 d1 = *(const int4*)(dst + base + 4);
        atomicAdd(&g_cnt[d0.x], 1); atomicAdd(&g_cnt[d0.y], 1);
        atomicAdd(&g_cnt[d0.z], 1); atomicAdd(&g_cnt[d0.w], 1);
        atomicAdd(&g_cnt[d1.x], 1); atomicAdd(&g_cnt[d1.y], 1);
        atomicAdd(&g_cnt[d1.z], 1); atomicAdd(&g_cnt[d1.w], 1);
    } else {
        for (int j = base; j < E; j++) atomicAdd(&g_cnt[dst[j]], 1);
    }
}

// phase 1: per-block (1024-elem) sums
__global__ void k_bsum(int n) {
    __shared__ int wsum[32];
    int tid = threadIdx.x, lane = tid & 31, wid = tid >> 5;
    int i = blockIdx.x * 1024 + tid;
    int v = (i < n) ? g_cnt[i] : 0;
    #pragma unroll
    for (int o = 16; o > 0; o >>= 1) v += __shfl_xor_sync(0xffffffffu, v, o);
    if (lane == 0) wsum[wid] = v;
    __syncthreads();
    if (wid == 0) {
        int w = wsum[lane];
        #pragma unroll
        for (int o = 16; o > 0; o >>= 1) w += __shfl_xor_sync(0xffffffffu, w, o);
        if (lane == 0) g_bsum[blockIdx.x] = w;
    }
}

// phase 2: exclusive scan of up to 64 block sums (1 block, 64 threads)
__global__ void k_scanb(int nb) {
    __shared__ int w0sum;
    int tid = threadIdx.x, lane = tid & 31, wid = tid >> 5;
    int v = (tid < nb) ? g_bsum[tid] : 0;
    int x = v;
    #pragma unroll
    for (int o = 1; o < 32; o <<= 1) {
        int t = __shfl_up_sync(0xffffffffu, x, o);
        if (lane >= o) x += t;
    }
    if (wid == 0 && lane == 31) w0sum = x;
    __syncthreads();
    if (wid == 1) x += w0sum;
    if (tid < nb) g_bsum[tid] = x - v;   // exclusive
}

// phase 3: block scan + global offset; write rowstart/cursor/dinv
__global__ void k_scan2(int n) {
    __shared__ int wsum[32];
    int tid = threadIdx.x, lane = tid & 31, wid = tid >> 5;
    int i = blockIdx.x * 1024 + tid;
    int v = (i < n) ? g_cnt[i] : 0;
    int x = v;
    #pragma unroll
    for (int o = 1; o < 32; o <<= 1) {
        int t = __shfl_up_sync(0xffffffffu, x, o);
        if (lane >= o) x += t;
    }
    if (lane == 31) wsum[wid] = x;
    __syncthreads();
    if (wid == 0) {
        int w = wsum[lane];
        #pragma unroll
        for (int o = 1; o < 32; o <<= 1) {
            int t = __shfl_up_sync(0xffffffffu, w, o);
            if (lane >= o) w += t;
        }
        wsum[lane] = w;
    }
    __syncthreads();
    int excl = g_bsum[blockIdx.x] + (wid > 0 ? wsum[wid - 1] : 0) + x - v;
    if (i < n) {
        g_rowstart[i] = excl;
        g_cursor[i]   = excl;
        g_dinv[i]     = rsqrtf((float)(v + 1));   // deg incl. self-loop
        if (i == n - 1) g_rowstart[n] = excl + v;
    }
}

__global__ void k_fill(const int* __restrict__ ei, int E) {
    int base = (blockIdx.x * blockDim.x + threadIdx.x) * 8;
    if (base >= E) return;
    if (base + 7 < E) {
        int ss[8], ds[8];
        *(int4*)(ss)     = *(const int4*)(ei + base);
        *(int4*)(ss + 4) = *(const int4*)(ei + base + 4);
        *(int4*)(ds)     = *(const int4*)(ei + E + base);
        *(int4*)(ds + 4) = *(const int4*)(ei + E + base + 4);
        float ws[8];
        #pragma unroll
        for (int j = 0; j < 8; j++) ws[j] = g_dinv[ss[j]] * g_dinv[ds[j]];
        #pragma unroll
        for (int j = 0; j < 8; j++) {
            int p = atomicAdd(&g_cursor[ds[j]], 1);
            g_cw[p] = make_int2(ss[j], __float_as_int(ws[j]));
        }
    } else {
        for (int j = base; j < E; j++) {
            int sj = ei[j], dj = ei[E + j];
            float w = g_dinv[sj] * g_dinv[dj];
            int p = atomicAdd(&g_cursor[dj], 1);
            g_cw[p] = make_int2(sj, __float_as_int(w));
        }
    }
}

// ---------------- GEMM: H[M x 128] = X @ W via 3xTF32 mma.m16n8k8 ----------------
// Block tile M=128, N=128, K chunked at 64. 8 warps: 4(M) x 2(N); warp tile 32x64.
// (R5-measured config: occupancy 1, no reg spill. Do NOT force 2 CTAs/SM — the
//  64-float accumulator file spills at the 128-reg cap.)
#define SXS 68    // X smem row stride (floats): A-frag bank = (4g+t)%32, bijective
#define SWS 136   // W smem row stride (floats): B-frag bank = (8t+g)%32, bijective
#define GEMM_SMEM ((2 * 128 * SXS + 2 * 64 * SWS) * (int)sizeof(float))

__global__ __launch_bounds__(256, 1)
void k_gemm_mma(const float* __restrict__ X, const float* __restrict__ W,
                float* __restrict__ H, int M) {
    extern __shared__ float sm[];
    float* sXh = sm;
    float* sXl = sXh + 128 * SXS;
    float* sWh = sXl + 128 * SXS;
    float* sWl = sWh + 64 * SWS;

    const int tid  = threadIdx.x;
    const int lane = tid & 31;
    const int g    = lane >> 2;
    const int t    = lane & 3;
    const int warp = tid >> 5;
    const int wm   = (warp >> 1) * 32;   // warp M offset
    const int wn   = (warp & 1) * 64;    // warp N offset
    const int row0 = blockIdx.x * 128;

    float acc[2][8][4];
    #pragma unroll
    for (int a = 0; a < 2; a++)
        #pragma unroll
        for (int b = 0; b < 8; b++)
            #pragma unroll
            for (int c = 0; c < 4; c++) acc[a][b][c] = 0.f;

    #pragma unroll
    for (int kc = 0; kc < 2; kc++) {
        // load X chunk [128 rows][64 cols] as 2048 float4
        #pragma unroll
        for (int it = 0; it < 8; it++) {
            int e4 = tid + it * 256;
            int r  = e4 >> 4;
            int c4 = (e4 & 15) * 4;
            float4 v = make_float4(0.f, 0.f, 0.f, 0.f);
            if (row0 + r < M)
                v = *(const float4*)&X[(size_t)(row0 + r) * D + kc * 64 + c4];
            float4 h, l;
            tf32_split(v.x, h.x, l.x);
            tf32_split(v.y, h.y, l.y);
            tf32_split(v.z, h.z, l.z);
            tf32_split(v.w, h.w, l.w);
            *(float4*)&sXh[r * SXS + c4] = h;
            *(float4*)&sXl[r * SXS + c4] = l;
        }
        // load W chunk [64 k][128 n] as 2048 float4
        #pragma unroll
        for (int it = 0; it < 8; it++) {
            int e4 = tid + it * 256;
            int r  = e4 >> 5;
            int c4 = (e4 & 31) * 4;
            float4 v = *(const float4*)&W[(size_t)(kc * 64 + r) * D + c4];
            float4 h, l;
            tf32_split(v.x, h.x, l.x);
            tf32_split(v.y, h.y, l.y);
            tf32_split(v.z, h.z, l.z);
            tf32_split(v.w, h.w, l.w);
            *(float4*)&sWh[r * SWS + c4] = h;
            *(float4*)&sWl[r * SWS + c4] = l;
        }
        __syncthreads();

        #pragma unroll
        for (int ks = 0; ks < 8; ks++) {
            int k0 = ks * 8;
            uint32_t ah[2][4], al[2][4];
            #pragma unroll
            for (int mi = 0; mi < 2; mi++) {
                int mb = wm + mi * 16;
                ah[mi][0] = __float_as_uint(sXh[(mb + g)     * SXS + k0 + t]);
                ah[mi][1] = __float_as_uint(sXh[(mb + g + 8) * SXS + k0 + t]);
                ah[mi][2] = __float_as_uint(sXh[(mb + g)     * SXS + k0 + t + 4]);
                ah[mi][3] = __float_as_uint(sXh[(mb + g + 8) * SXS + k0 + t + 4]);
                al[mi][0] = __float_as_uint(sXl[(mb + g)     * SXS + k0 + t]);
                al[mi][1] = __float_as_uint(sXl[(mb + g + 8) * SXS + k0 + t]);
                al[mi][2] = __float_as_uint(sXl[(mb + g)     * SXS + k0 + t + 4]);
                al[mi][3] = __float_as_uint(sXl[(mb + g + 8) * SXS + k0 + t + 4]);
            }
            #pragma unroll
            for (int j = 0; j < 8; j++) {
                int nb = wn + j * 8;
                uint32_t bh0 = __float_as_uint(sWh[(k0 + t)     * SWS + nb + g]);
                uint32_t bh1 = __float_as_uint(sWh[(k0 + t + 4) * SWS + nb + g]);
                uint32_t bl0 = __float_as_uint(sWl[(k0 + t)     * SWS + nb + g]);
                uint32_t bl1 = __float_as_uint(sWl[(k0 + t + 4) * SWS + nb + g]);
                #pragma unroll
                for (int mi = 0; mi < 2; mi++) {
                    mma_tf32(acc[mi][j], ah[mi], bh0, bh1);
                    mma_tf32(acc[mi][j], ah[mi], bl0, bl1);
                    mma_tf32(acc[mi][j], al[mi], bh0, bh1);
                }
            }
        }
        __syncthreads();
    }

    #pragma unroll
    for (int mi = 0; mi < 2; mi++) {
        int r0 = row0 + wm + mi * 16 + g;
        #pragma unroll
        for (int j = 0; j < 8; j++) {
            int col = wn + j * 8 + 2 * t;
            if (r0 < M)
                *(float2*)&H[(size_t)r0 * D + col] =
                    make_float2(acc[mi][j][0], acc[mi][j][1]);
            if (r0 + 8 < M)
                *(float2*)&H[(size_t)(r0 + 8) * D + col] =
                    make_float2(acc[mi][j][2], acc[mi][j][3]);
        }
    }
}

// ---------------- aggregation: Y[n] = relu?( dinv^2*H[n] + sum w_i*H[col_i] + b )
__global__ void k_agg(const float* __restrict__ bias, float* __restrict__ Y,
                      int n, int do_relu) {
    int gt   = blockIdx.x * blockDim.x + threadIdx.x;
    int node = gt >> 5;
    int lane = gt & 31;
    if (node >= n) return;

    const float4* H4 = (const float4*)g_H;
    float di = g_dinv[node];
    float4 acc = H4[(size_t)node * 32 + lane];
    float sw = di * di;
    acc.x *= sw; acc.y *= sw; acc.z *= sw; acc.w *= sw;

    int i   = g_rowstart[node];
    int end = g_rowstart[node + 1];
    for (; i + 1 < end; i += 2) {
        int2  e0 = g_cw[i];
        int2  e1 = g_cw[i + 1];
        float w0 = __int_as_float(e0.y);
        float w1 = __int_as_float(e1.y);
        float4 h0 = H4[(size_t)e0.x * 32 + lane];
        float4 h1 = H4[(size_t)e1.x * 32 + lane];
        acc.x += w0 * h0.x + w1 * h1.x;
        acc.y += w0 * h0.y + w1 * h1.y;
        acc.z += w0 * h0.z + w1 * h1.z;
        acc.w += w0 * h0.w + w1 * h1.w;
    }
    if (i < end) {
        int2  e = g_cw[i];
        float w = __int_as_float(e.y);
        float4 h = H4[(size_t)e.x * 32 + lane];
        acc.x += w * h.x; acc.y += w * h.y; acc.z += w * h.z; acc.w += w * h.w;
    }

    float4 b4 = ((const float4*)bias)[lane];
    acc.x += b4.x; acc.y += b4.y; acc.z += b4.z; acc.w += b4.w;
    if (do_relu) {
        acc.x = fmaxf(acc.x, 0.f); acc.y = fmaxf(acc.y, 0.f);
        acc.z = fmaxf(acc.z, 0.f); acc.w = fmaxf(acc.w, 0.f);
    }
    ((float4*)Y)[(size_t)node * 32 + lane] = acc;
}

// ---------------- decoder: out[e] = dot(X[u], X[v]) ----------------
__global__ void k_decode(const float* __restrict__ X, const int* __restrict__ eli,
                         float* __restrict__ out, int EL) {
    int gt   = blockIdx.x * blockDim.x + threadIdx.x;
    int e    = gt >> 5;
    int lane = gt & 31;
    if (e >= EL) return;
    int u = eli[e];
    int v = eli[EL + e];
    const float4* X4 = (const float4*)X;
    float4 a = X4[(size_t)u * 32 + lane];
    float4 b = X4[(size_t)v * 32 + lane];
    float s = a.x * b.x + a.y * b.y + a.z * b.z + a.w * b.w;
    #pragma unroll
    for (int o = 16; o > 0; o >>= 1) s += __shfl_xor_sync(0xffffffffu, s, o);
    if (lane == 0) out[e] = s;
}

// ---------------- launch ----------------
extern "C" void kernel_launch(void* const* d_in, const int* in_sizes, int n_in,
                              void* d_out, int out_size) {
    const float* x   = (const float*)d_in[0];
    const float* W1  = (const float*)d_in[1];
    const float* b1  = (const float*)d_in[2];
    const float* W2  = (const float*)d_in[3];
    const float* b2  = (const float*)d_in[4];
    const float* W3  = (const float*)d_in[5];
    const float* b3  = (const float*)d_in[6];
    const int*   ei  = (const int*)d_in[7];
    const int*   eli = (const int*)d_in[8];
    float*       out = (float*)d_out;

    int N  = in_sizes[0] / D;
    int E  = in_sizes[7] / 2;
    int EL = in_sizes[8] / 2;

    float *pH, *pA, *pB;
    cudaGetSymbolAddress((void**)&pH, g_H);
    cudaGetSymbolAddress((void**)&pA, g_A);
    cudaGetSymbolAddress((void**)&pB, g_B);

    cudaFuncSetAttribute(k_gemm_mma, cudaFuncAttributeMaxDynamicSharedMemorySize,
                         GEMM_SMEM);

    // ---- CSR build (once; shared by all 3 layers) ----
    int nb = (N + 1023) / 1024;
    k_zero_cnt<<<(N + 255) / 256, 256>>>(N);
    k_count<<<(E / 8 + 255) / 256, 256>>>(ei + E, E);
    k_bsum<<<nb, 1024>>>(N);
    k_scanb<<<1, 64>>>(nb);
    k_scan2<<<nb, 1024>>>(N);
    k_fill<<<(E / 8 + 255) / 256, 256>>>(ei, E);

    int gemm_blocks = (N + 127) / 128;
    int agg_blocks  = (int)(((size_t)N * 32 + 255) / 256);

    // ---- layer 1 ----
    k_gemm_mma<<<gemm_blocks, 256, GEMM_SMEM>>>(x, W1, pH, N);
    k_agg<<<agg_blocks, 256>>>(b1, pA, N, 1);

    // ---- layer 2 ----
    k_gemm_mma<<<gemm_blocks, 256, GEMM_SMEM>>>(pA, W2, pH, N);
    k_agg<<<agg_blocks, 256>>>(b2, pB, N, 1);

    // ---- layer 3 (no relu) ----
    k_gemm_mma<<<gemm_blocks, 256, GEMM_SMEM>>>(pB, W3, pH, N);
    k_agg<<<agg_blocks, 256>>>(b3, pA, N, 0);

    // ---- decoder ----
    k_decode<<<(int)(((size_t)EL * 32 + 255) / 256), 256>>>(pA, eli, out, EL);
}

// round 12
// speedup vs baseline: 1.4236x; 1.0375x over previous
#include <cuda_runtime.h>
#include <cstdint>

#define D 128
#define NMAX 50000
#define EMAX 800000

// ---------------- scratch (static device globals; no allocation) ----------------
__device__ float g_H [(size_t)NMAX * D];   // GEMM output per layer
__device__ float g_A [(size_t)NMAX * D];   // layer activations (ping)
__device__ float g_B [(size_t)NMAX * D];   // layer activations (pong)
__device__ float g_dinv[NMAX];
__device__ int   g_cnt[NMAX];              // invariant: zero at entry of every call
__device__ int   g_rowstart[NMAX + 1];
__device__ int   g_cursor[NMAX];
__device__ int2  g_cw[EMAX];               // packed (src, weight-bits)
__device__ unsigned long long g_desc[64];  // lookback descriptors (zero at entry)

// ---------------- capture-safe static stream/events (host resources only) ------
static cudaStream_t s2;
static cudaEvent_t  evFork, evJoin;
namespace { struct _Init {
    _Init() {
        cudaStreamCreateWithFlags(&s2, cudaStreamNonBlocking);
        cudaEventCreateWithFlags(&evFork, cudaEventDisableTiming);
        cudaEventCreateWithFlags(&evJoin, cudaEventDisableTiming);
    }
} _init; }

// ---------------- tf32 helpers ----------------
__device__ __forceinline__ void tf32_split(float x, float& h, float& l) {
    uint32_t hb; asm("cvt.rna.tf32.f32 %0, %1;" : "=r"(hb) : "f"(x));
    h = __uint_as_float(hb);
    float r = x - h;
    uint32_t lb; asm("cvt.rna.tf32.f32 %0, %1;" : "=r"(lb) : "f"(r));
    l = __uint_as_float(lb);
}

__device__ __forceinline__ void mma_tf32(float* c, const uint32_t* a,
                                         uint32_t b0, uint32_t b1) {
    asm volatile(
        "mma.sync.aligned.m16n8k8.row.col.f32.tf32.tf32.f32 "
        "{%0,%1,%2,%3}, {%4,%5,%6,%7}, {%8,%9}, {%0,%1,%2,%3};"
        : "+f"(c[0]), "+f"(c[1]), "+f"(c[2]), "+f"(c[3])
        : "r"(a[0]), "r"(a[1]), "r"(a[2]), "r"(a[3]), "r"(b0), "r"(b1));
}

// ---------------- CSR construction ----------------
__global__ void k_count(const int* __restrict__ dst, int E) {
    int base = (blockIdx.x * blockDim.x + threadIdx.x) * 4;
    if (base >= E) return;
    if (base + 3 < E) {
        int4 d = *(const int4*)(dst + base);
        atomicAdd(&g_cnt[d.x], 1);
        atomicAdd(&g_cnt[d.y], 1);
        atomicAdd(&g_cnt[d.z], 1);
        atomicAdd(&g_cnt[d.w], 1);
    } else {
        for (int j = base; j < E; j++) atomicAdd(&g_cnt[dst[j]], 1);
    }
}

// single-pass exclusive scan via decoupled lookback; writes rowstart/cursor/dinv.
// Also re-zeroes g_cnt (self-cleaning invariant). 49 blocks <= 148 SMs, all
// co-resident; each block only polls lower block-ids -> no deadlock.
__global__ void k_scan_lb(int n) {
    __shared__ int wsum[32];
    __shared__ int s_prefix;
    int tid = threadIdx.x, lane = tid & 31, wid = tid >> 5;
    int b = blockIdx.x;
    int i = b * 1024 + tid;
    int v = (i < n) ? g_cnt[i] : 0;
    if (i < n) g_cnt[i] = 0;               // self-clean for next replay
    int x = v;
    #pragma unroll
    for (int o = 1; o < 32; o <<= 1) {
        int t = __shfl_up_sync(0xffffffffu, x, o);
        if (lane >= o) x += t;
    }
    if (lane == 31) wsum[wid] = x;
    __syncthreads();
    if (wid == 0) {
        int w = wsum[lane];
        #pragma unroll
        for (int o = 1; o < 32; o <<= 1) {
            int t = __shfl_up_sync(0xffffffffu, w, o);
            if (lane >= o) w += t;
        }
        wsum[lane] = w;
    }
    __syncthreads();
    int blockAgg = wsum[31];

    if (tid == 0) {
        if (b == 0) {
            s_prefix = 0;
            atomicExch(&g_desc[0], (2ULL << 32) | (unsigned)blockAgg);
        } else {
            atomicExch(&g_desc[b], (1ULL << 32) | (unsigned)blockAgg);
        }
    }
    if (b > 0 && wid == 0) {
        int prefix = 0;
        int look = b - 1;
        while (true) {
            int idx = look - lane;
            unsigned f; int val;
            if (idx >= 0) {
                unsigned long long d = atomicAdd(&g_desc[idx], 0ULL);
                f = (unsigned)(d >> 32);
                val = (int)(unsigned)d;
            } else { f = 1u; val = 0; }
            if (__ballot_sync(0xffffffffu, f == 0u)) continue;   // retry window
            unsigned bp = __ballot_sync(0xffffffffu, idx >= 0 && f == 2u);
            int stop = bp ? (__ffs(bp) - 1) : 32;
            int xs = (lane <= stop) ? val : 0;
            #pragma unroll
            for (int o = 16; o > 0; o >>= 1)
                xs += __shfl_xor_sync(0xffffffffu, xs, o);
            prefix += xs;
            if (stop < 32) break;
            look -= 32;
        }
        if (lane == 0) {
            s_prefix = prefix;
            atomicExch(&g_desc[b], (2ULL << 32) | (unsigned)(prefix + blockAgg));
        }
    }
    __syncthreads();

    int excl = s_prefix + (wid ? wsum[wid - 1] : 0) + x - v;
    if (i < n) {
        g_rowstart[i] = excl;
        g_cursor[i]   = excl;
        g_dinv[i]     = rsqrtf((float)(v + 1));   // deg incl. self-loop
        if (i == n - 1) g_rowstart[n] = excl + v;
    }
}

__global__ void k_fill(const int* __restrict__ ei, int E) {
    // re-zero the lookback descriptors for the next replay (scan is complete)
    if (blockIdx.x == 0 && threadIdx.x < 64) g_desc[threadIdx.x] = 0ULL;
    int base = (blockIdx.x * blockDim.x + threadIdx.x) * 4;
    if (base >= E) return;
    if (base + 3 < E) {
        int4 s = *(const int4*)(ei + base);
        int4 d = *(const int4*)(ei + E + base);
        int ss[4] = {s.x, s.y, s.z, s.w};
        int ds[4] = {d.x, d.y, d.z, d.w};
        float ws[4];
        #pragma unroll
        for (int j = 0; j < 4; j++) ws[j] = g_dinv[ss[j]] * g_dinv[ds[j]];
        #pragma unroll
        for (int j = 0; j < 4; j++) {
            int p = atomicAdd(&g_cursor[ds[j]], 1);
            g_cw[p] = make_int2(ss[j], __float_as_int(ws[j]));
        }
    } else {
        for (int j = base; j < E; j++) {
            int sj = ei[j], dj = ei[E + j];
            float w = g_dinv[sj] * g_dinv[dj];
            int p = atomicAdd(&g_cursor[dj], 1);
            g_cw[p] = make_int2(sj, __float_as_int(w));
        }
    }
}

// ---------------- GEMM: H[M x 128] = X @ W via 3xTF32 mma.m16n8k8 ----------------
// Block tile M=128, N=128, K chunked at 64. 8 warps: 4(M) x 2(N); warp tile 32x64.
// Measured-good config: occupancy 1 (do NOT force 2 CTAs/SM; accumulators spill).
#define SXS 68    // X smem row stride (floats): A-frag bank = (4g+t)%32, bijective
#define SWS 136   // W smem row stride (floats): B-frag bank = (8t+g)%32, bijective
#define GEMM_SMEM ((2 * 128 * SXS + 2 * 64 * SWS) * (int)sizeof(float))

__global__ __launch_bounds__(256, 1)
void k_gemm_mma(const float* __restrict__ X, const float* __restrict__ W,
                float* __restrict__ H, int M) {
    extern __shared__ float sm[];
    float* sXh = sm;
    float* sXl = sXh + 128 * SXS;
    float* sWh = sXl + 128 * SXS;
    float* sWl = sWh + 64 * SWS;

    const int tid  = threadIdx.x;
    const int lane = tid & 31;
    const int g    = lane >> 2;
    const int t    = lane & 3;
    const int warp = tid >> 5;
    const int wm   = (warp >> 1) * 32;   // warp M offset
    const int wn   = (warp & 1) * 64;    // warp N offset
    const int row0 = blockIdx.x * 128;

    float acc[2][8][4];
    #pragma unroll
    for (int a = 0; a < 2; a++)
        #pragma unroll
        for (int b = 0; b < 8; b++)
            #pragma unroll
            for (int c = 0; c < 4; c++) acc[a][b][c] = 0.f;

    #pragma unroll
    for (int kc = 0; kc < 2; kc++) {
        // load X chunk [128 rows][64 cols] as 2048 float4
        #pragma unroll
        for (int it = 0; it < 8; it++) {
            int e4 = tid + it * 256;
            int r  = e4 >> 4;
            int c4 = (e4 & 15) * 4;
            float4 v = make_float4(0.f, 0.f, 0.f, 0.f);
            if (row0 + r < M)
                v = *(const float4*)&X[(size_t)(row0 + r) * D + kc * 64 + c4];
            float4 h, l;
            tf32_split(v.x, h.x, l.x);
            tf32_split(v.y, h.y, l.y);
            tf32_split(v.z, h.z, l.z);
            tf32_split(v.w, h.w, l.w);
            *(float4*)&sXh[r * SXS + c4] = h;
            *(float4*)&sXl[r * SXS + c4] = l;
        }
        // load W chunk [64 k][128 n] as 2048 float4
        #pragma unroll
        for (int it = 0; it < 8; it++) {
            int e4 = tid + it * 256;
            int r  = e4 >> 5;
            int c4 = (e4 & 31) * 4;
            float4 v = *(const float4*)&W[(size_t)(kc * 64 + r) * D + c4];
            float4 h, l;
            tf32_split(v.x, h.x, l.x);
            tf32_split(v.y, h.y, l.y);
            tf32_split(v.z, h.z, l.z);
            tf32_split(v.w, h.w, l.w);
            *(float4*)&sWh[r * SWS + c4] = h;
            *(float4*)&sWl[r * SWS + c4] = l;
        }
        __syncthreads();

        #pragma unroll
        for (int ks = 0; ks < 8; ks++) {
            int k0 = ks * 8;
            uint32_t ah[2][4], al[2][4];
            #pragma unroll
            for (int mi = 0; mi < 2; mi++) {
                int mb = wm + mi * 16;
                ah[mi][0] = __float_as_uint(sXh[(mb + g)     * SXS + k0 + t]);
                ah[mi][1] = __float_as_uint(sXh[(mb + g + 8) * SXS + k0 + t]);
                ah[mi][2] = __float_as_uint(sXh[(mb + g)     * SXS + k0 + t + 4]);
                ah[mi][3] = __float_as_uint(sXh[(mb + g + 8) * SXS + k0 + t + 4]);
                al[mi][0] = __float_as_uint(sXl[(mb + g)     * SXS + k0 + t]);
                al[mi][1] = __float_as_uint(sXl[(mb + g + 8) * SXS + k0 + t]);
                al[mi][2] = __float_as_uint(sXl[(mb + g)     * SXS + k0 + t + 4]);
                al[mi][3] = __float_as_uint(sXl[(mb + g + 8) * SXS + k0 + t + 4]);
            }
            #pragma unroll
            for (int j = 0; j < 8; j++) {
                int nb = wn + j * 8;
                uint32_t bh0 = __float_as_uint(sWh[(k0 + t)     * SWS + nb + g]);
                uint32_t bh1 = __float_as_uint(sWh[(k0 + t + 4) * SWS + nb + g]);
                uint32_t bl0 = __float_as_uint(sWl[(k0 + t)     * SWS + nb + g]);
                uint32_t bl1 = __float_as_uint(sWl[(k0 + t + 4) * SWS + nb + g]);
                #pragma unroll
                for (int mi = 0; mi < 2; mi++) {
                    mma_tf32(acc[mi][j], ah[mi], bh0, bh1);
                    mma_tf32(acc[mi][j], ah[mi], bl0, bl1);
                    mma_tf32(acc[mi][j], al[mi], bh0, bh1);
                }
            }
        }
        __syncthreads();
    }

    #pragma unroll
    for (int mi = 0; mi < 2; mi++) {
        int r0 = row0 + wm + mi * 16 + g;
        #pragma unroll
        for (int j = 0; j < 8; j++) {
            int col = wn + j * 8 + 2 * t;
            if (r0 < M)
                *(float2*)&H[(size_t)r0 * D + col] =
                    make_float2(acc[mi][j][0], acc[mi][j][1]);
            if (r0 + 8 < M)
                *(float2*)&H[(size_t)(r0 + 8) * D + col] =
                    make_float2(acc[mi][j][2], acc[mi][j][3]);
        }
    }
}

// ---------------- aggregation: Y[n] = relu?( dinv^2*H[n] + sum w_i*H[col_i] + b )
__global__ void k_agg(const float* __restrict__ bias, float* __restrict__ Y,
                      int n, int do_relu) {
    int gt   = blockIdx.x * blockDim.x + threadIdx.x;
    int node = gt >> 5;
    int lane = gt & 31;
    if (node >= n) return;

    const float4* H4 = (const float4*)g_H;
    float di = g_dinv[node];
    float4 acc = H4[(size_t)node * 32 + lane];
    float sw = di * di;
    acc.x *= sw; acc.y *= sw; acc.z *= sw; acc.w *= sw;

    int i   = g_rowstart[node];
    int end = g_rowstart[node + 1];
    // 4-wide unroll: independent index loads + gathers for MLP
    for (; i + 3 < end; i += 4) {
        int2  e0 = g_cw[i],     e1 = g_cw[i + 1];
        int2  e2 = g_cw[i + 2], e3 = g_cw[i + 3];
        float w0 = __int_as_float(e0.y), w1 = __int_as_float(e1.y);
        float w2 = __int_as_float(e2.y), w3 = __int_as_float(e3.y);
        float4 h0 = H4[(size_t)e0.x * 32 + lane];
        float4 h1 = H4[(size_t)e1.x * 32 + lane];
        float4 h2 = H4[(size_t)e2.x * 32 + lane];
        float4 h3 = H4[(size_t)e3.x * 32 + lane];
        acc.x += w0 * h0.x + w1 * h1.x + w2 * h2.x + w3 * h3.x;
        acc.y += w0 * h0.y + w1 * h1.y + w2 * h2.y + w3 * h3.y;
        acc.z += w0 * h0.z + w1 * h1.z + w2 * h2.z + w3 * h3.z;
        acc.w += w0 * h0.w + w1 * h1.w + w2 * h2.w + w3 * h3.w;
    }
    for (; i < end; i++) {
        int2  e = g_cw[i];
        float w = __int_as_float(e.y);
        float4 h = H4[(size_t)e.x * 32 + lane];
        acc.x += w * h.x; acc.y += w * h.y; acc.z += w * h.z; acc.w += w * h.w;
    }

    float4 b4 = ((const float4*)bias)[lane];
    acc.x += b4.x; acc.y += b4.y; acc.z += b4.z; acc.w += b4.w;
    if (do_relu) {
        acc.x = fmaxf(acc.x, 0.f); acc.y = fmaxf(acc.y, 0.f);
        acc.z = fmaxf(acc.z, 0.f); acc.w = fmaxf(acc.w, 0.f);
    }
    ((float4*)Y)[(size_t)node * 32 + lane] = acc;
}

// ---------------- decoder: out[e] = dot(X[u], X[v]) ----------------
__global__ void k_decode(const float* __restrict__ X, const int* __restrict__ eli,
                         float* __restrict__ out, int EL) {
    int gt   = blockIdx.x * blockDim.x + threadIdx.x;
    int e    = gt >> 5;
    int lane = gt & 31;
    if (e >= EL) return;
    int u = eli[e];
    int v = eli[EL + e];
    const float4* X4 = (const float4*)X;
    float4 a = X4[(size_t)u * 32 + lane];
    float4 b = X4[(size_t)v * 32 + lane];
    float s = a.x * b.x + a.y * b.y + a.z * b.z + a.w * b.w;
    #pragma unroll
    for (int o = 16; o > 0; o >>= 1) s += __shfl_xor_sync(0xffffffffu, s, o);
    if (lane == 0) out[e] = s;
}

// ---------------- launch ----------------
extern "C" void kernel_launch(void* const* d_in, const int* in_sizes, int n_in,
                              void* d_out, int out_size) {
    const float* x   = (const float*)d_in[0];
    const float* W1  = (const float*)d_in[1];
    const float* b1  = (const float*)d_in[2];
    const float* W2  = (const float*)d_in[3];
    const float* b2  = (const float*)d_in[4];
    const float* W3  = (const float*)d_in[5];
    const float* b3  = (const float*)d_in[6];
    const int*   ei  = (const int*)d_in[7];
    const int*   eli = (const int*)d_in[8];
    float*       out = (float*)d_out;

    int N  = in_sizes[0] / D;
    int E  = in_sizes[7] / 2;
    int EL = in_sizes[8] / 2;

    float *pH, *pA, *pB;
    cudaGetSymbolAddress((void**)&pH, g_H);
    cudaGetSymbolAddress((void**)&pA, g_A);
    cudaGetSymbolAddress((void**)&pB, g_B);

    cudaFuncSetAttribute(k_gemm_mma, cudaFuncAttributeMaxDynamicSharedMemorySize,
                         GEMM_SMEM);

    int nb          = (N + 1023) / 1024;
    int gemm_blocks = (N + 127) / 128;
    int agg_blocks  = (int)(((size_t)N * 32 + 255) / 256);

    // ---- fork: CSR build on s2, concurrent with GEMM layer 1 on stream 0 ----
    cudaEventRecord(evFork, 0);
    cudaStreamWaitEvent(s2, evFork, 0);
    k_count  <<<(E / 4 + 255) / 256, 256, 0, s2>>>(ei + E, E);
    k_scan_lb<<<nb, 1024, 0, s2>>>(N);
    k_fill   <<<(E / 4 + 255) / 256, 256, 0, s2>>>(ei, E);
    cudaEventRecord(evJoin, s2);

    // ---- layer 1 GEMM overlaps the CSR build ----
    k_gemm_mma<<<gemm_blocks, 256, GEMM_SMEM>>>(x, W1, pH, N);

    // ---- join: agg needs both GEMM-1 output and the CSR ----
    cudaStreamWaitEvent(0, evJoin, 0);
    k_agg<<<agg_blocks, 256>>>(b1, pA, N, 1);

    // ---- layer 2 ----
    k_gemm_mma<<<gemm_blocks, 256, GEMM_SMEM>>>(pA, W2, pH, N);
    k_agg<<<agg_blocks, 256>>>(b2, pB, N, 1);

    // ---- layer 3 (no relu) ----
    k_gemm_mma<<<gemm_blocks, 256, GEMM_SMEM>>>(pB, W3, pH, N);
    k_agg<<<agg_blocks, 256>>>(b3, pA, N, 0);

    // ---- decoder ----
    k_decode<<<(int)(((size_t)EL * 32 + 255) / 256), 256>>>(pA, eli, out, EL);
}